// round 3
// baseline (speedup 1.0000x reference)
#include <cuda_runtime.h>
#include <cuda_bf16.h>

#define RIR_LEN   8000
#define NIMG      1561
#define NTH       512
#define PI_F      3.14159265358979323846f
#define FS_OVER_C 46.64723032069971f   /* 16000 / 343 */

__global__ void __launch_bounds__(NTH)
ShoeboxToRIR_kernel(const float* __restrict__ in, float* __restrict__ out, int B)
{
    __shared__ float srir[RIR_LEN];   // 32000 B
    __shared__ float prm[10];
    __shared__ float trp[11];         // tr^k, k=0..10
    __shared__ int   pfx[22];         // image-index prefix per gx shell

    const int b   = blockIdx.x;
    const int tid = threadIdx.x;

    if (tid < 10) prm[tid] = in[b * 10 + tid];
    if (tid < 22) {
        // S(n) = sum_{m=0}^{n-1} (2m^2+2m+1); pfx[gxi] = start index of gx = gxi-10
        int n = tid, v;
        if (n <= 10) {
            v = (n - 1) * n * (2 * n - 1) / 3 + (n - 1) * n + n;
        } else {
            int m = 21 - n;
            v = NIMG - ((m - 1) * m * (2 * m - 1) / 3 + (m - 1) * m + m);
        }
        pfx[tid] = v;
    }
    __syncthreads();

    float room[3], mic[3], src[3];
#pragma unroll
    for (int d = 0; d < 3; d++) {
        room[d] = prm[d];
        mic[d]  = prm[3 + d] * room[d];
        src[d]  = prm[6 + d] * room[d];
    }
    float tr = sqrtf(1.0f - prm[9]);
    if (tid < 11) trp[tid] = powf(tr, (float)tid);
    for (int i = tid; i < RIR_LEN; i += NTH) srir[i] = 0.0f;
    __syncthreads();

    // Hann recurrence step constants: cos(pi/40), sin(pi/40)
    const float dc  = 0.9969173337331280f;
    const float dsn = 0.07845909572784494f;

    for (int i = tid; i < NIMG; i += NTH) {
        // ---- decode image index -> (gx, gy, gz), |gx|+|gy|+|gz| <= 10 ----
        int lo = 0, hi = 21;
#pragma unroll
        for (int it = 0; it < 5; it++) {          // binary search over pfx
            int mid = (lo + hi) >> 1;
            if (i >= pfx[mid]) lo = mid; else hi = mid;
        }
        const int gxi = lo;
        const int gx  = gxi - 10;
        const int ax  = gx < 0 ? -gx : gx;
        const int R   = 10 - ax;                  // 2D L1 budget for (gy,gz)
        const int j   = i - pfx[gxi];
        const int M   = 2 * R * R + 2 * R + 1;
        const int rp1 = R + 1;
        int k;
        if (j < rp1 * rp1) k = (int)sqrtf((float)j + 0.5f);
        else               k = 2 * R - (int)sqrtf((float)(M - 1 - j) + 0.5f);
        const int Pk = (k <= R) ? k * k : M - (2 * R + 1 - k) * (2 * R + 1 - k);
        const int gy = k - R;
        const int ay = gy < 0 ? -gy : gy;
        const int gz = (j - Pk) - (R - ay);
        const int az = gz < 0 ? -gz : gz;

        // ---- per-image physics ----
        const float att = trp[ax + ay + az];      // tr^(L1 norm)
        const int g3[3] = {gx, gy, gz};
        float d2 = 0.0f;
#pragma unroll
        for (int d = 0; d < 3; d++) {
            const int   g  = g3[d];
            const float gf = (float)g;
            const float ip = (g & 1) ? room[d] * (gf + 1.0f) - src[d]
                                     : room[d] * gf + src[d];
            const float df = ip - mic[d];
            d2 += df * df;
        }
        const float dist    = sqrtf(d2);
        const float amp     = __fdividef(att, dist);
        const float delay   = dist * FS_OVER_C;
        const float delay_i = ceilf(delay);
        const float frac    = delay_i - delay;    // in [0,1)

        // sin(pi*(n+frac)) = (-1)^n * sin(pi*frac): one sinf per image
        const float s    = sinf(PI_F * frac);
        const float amps = amp * s;

        // Hann: cos(pi*x/40) via rotation recurrence, start at x0 = frac-40
        float sc, cc;
        __sincosf(PI_F * (1.0f / 40.0f) * frac, &sc, &cc);
        float cw = -cc, sw = -sc;                 // cos/sin(pi*(frac-40)/40)

        const int base = (int)delay_i - 40;
        float x   = frac - 40.0f;
        float sgn = 1.0f;                         // (-1)^(t-40), t=0 -> +1
#pragma unroll 3
        for (int t = 0; t < 81; t++) {
            const float hann = 0.5f + 0.5f * cw;
            const float sv   = (x == 0.0f) ? amp
                             : sgn * amps * __fdividef(1.0f, PI_F * x);
            const float val  = sv * hann;
            const int   idx  = base + t;
            if (x <= 40.0f && idx >= 0 && idx < RIR_LEN)
                atomicAdd(&srir[idx], val);
            const float cn = cw * dc - sw * dsn;  // rotate by pi/40
            sw = sw * dc + cw * dsn;
            cw = cn;
            x += 1.0f;
            sgn = -sgn;
        }
    }
    __syncthreads();

    // ---- write RIR row (coalesced) + TOA ----
    float* orow = out + (size_t)b * RIR_LEN;
    for (int i = tid; i < RIR_LEN; i += NTH) orow[i] = srir[i];
    if (tid == 0) {
        const float d0 = mic[0] - src[0];
        const float d1 = mic[1] - src[1];
        const float d2v = mic[2] - src[2];
        const float dms = sqrtf(d0 * d0 + d1 * d1 + d2v * d2v);
        out[(size_t)B * RIR_LEN + b] = 40.0f + FS_OVER_C * dms;
    }
}

extern "C" void kernel_launch(void* const* d_in, const int* in_sizes, int n_in,
                              void* d_out, int out_size)
{
    const float* in  = (const float*)d_in[0];
    float*       out = (float*)d_out;
    const int B = in_sizes[0] / 10;   // 256 rows of 10 floats
    ShoeboxToRIR_kernel<<<B, NTH>>>(in, out, B);
}

// round 5
// speedup vs baseline: 1.1112x; 1.1112x over previous
#include <cuda_runtime.h>
#include <cuda_bf16.h>

#define RIR_LEN   8000
#define NIMG      1561
#define NSPLIT    4
#define NTH       256
#define NWARP     (NTH / 32)
#define PI_F      3.14159265358979323846f
#define INV_PI_F  0.3183098861837907f
#define FS_OVER_C 46.64723032069971f   /* 16000 / 343 */
#define MAXB      256

// Partial RIRs: layout part[sub][b][t]  (sub-major) so combine reads are coalesced.
__device__ float g_part[NSPLIT * MAXB * RIR_LEN];

__global__ void __launch_bounds__(NTH, 7)
rir_partial_kernel(const float* __restrict__ in, float* __restrict__ out, int B)
{
    __shared__ float  srir[RIR_LEN];     // 32000 B
    __shared__ float2 htab[81];          // (cos,sin)(pi*(t-40)/40)
    __shared__ float  prm[10];
    __shared__ float  roomS[3], micS[3], srcS[3];
    __shared__ float  trp[11];           // tr^k
    __shared__ int    pfx[22];           // image-index prefix per gx shell

    const int b   = blockIdx.x >> 2;     // room
    const int sub = blockIdx.x & 3;      // image-range split
    const int tid = threadIdx.x;
    const int lane = tid & 31;
    const int warp = tid >> 5;

    if (tid < 10) prm[tid] = in[b * 10 + tid];
    if (tid < 22) {
        int n = tid, v;
        if (n <= 10) v = (n - 1) * n * (2 * n - 1) / 3 + (n - 1) * n + n;
        else { int m = 21 - n; v = NIMG - ((m - 1) * m * (2 * m - 1) / 3 + (m - 1) * m + m); }
        pfx[tid] = v;
    }
    if (tid < 81) {
        float sc, cc;
        sincosf(PI_F * (1.0f / 40.0f) * (float)(tid - 40), &sc, &cc);
        htab[tid] = make_float2(cc, sc);
    }
    for (int i = tid; i < RIR_LEN; i += NTH) srir[i] = 0.0f;
    __syncthreads();

    if (tid < 3) {
        float r = prm[tid];
        roomS[tid] = r;
        micS[tid]  = prm[3 + tid] * r;
        srcS[tid]  = prm[6 + tid] * r;
    }
    if (tid < 11) trp[tid] = powf(sqrtf(1.0f - prm[9]), (float)tid);
    __syncthreads();

    const int is = (NIMG * sub)       / NSPLIT;
    const int ie = (NIMG * (sub + 1)) / NSPLIT;

    for (int i0 = is + warp * 32; i0 < ie; i0 += NWARP * 32) {
        const int i = i0 + lane;

        // ---------- lane-parallel per-image scalar phase ----------
        float frL = 0.0f, a2L = 0.0f, amL = 0.0f, hcL = 0.0f, hsL = 0.0f;
        int baseL = 0;
        if (i < ie) {
            // decode image index -> (gx, gy, gz), |gx|+|gy|+|gz| <= 10
            int lo = 0, hi = 21;
#pragma unroll
            for (int it = 0; it < 5; it++) {
                int mid = (lo + hi) >> 1;
                if (i >= pfx[mid]) lo = mid; else hi = mid;
            }
            const int gx = lo - 10;
            const int ax = gx < 0 ? -gx : gx;
            const int R  = 10 - ax;
            const int j  = i - pfx[lo];
            const int M  = 2 * R * R + 2 * R + 1;
            const int rp1 = R + 1;
            int k;
            if (j < rp1 * rp1) k = (int)sqrtf((float)j + 0.5f);
            else               k = 2 * R - (int)sqrtf((float)(M - 1 - j) + 0.5f);
            const int Pk = (k <= R) ? k * k : M - (2 * R + 1 - k) * (2 * R + 1 - k);
            const int gy = k - R;
            const int ay = gy < 0 ? -gy : gy;
            const int gz = (j - Pk) - (R - ay);
            const int az = gz < 0 ? -gz : gz;

            const float att = trp[ax + ay + az];
            const int g3[3] = {gx, gy, gz};
            float d2 = 0.0f;
#pragma unroll
            for (int d = 0; d < 3; d++) {
                const int   g  = g3[d];
                const float gf = (float)g;
                const float ip = (g & 1) ? roomS[d] * (gf + 1.0f) - srcS[d]
                                         : roomS[d] * gf + srcS[d];
                const float df = ip - micS[d];
                d2 += df * df;
            }
            const float dist    = sqrtf(d2);
            const float amp     = __fdividef(att, dist);
            const float delay   = dist * FS_OVER_C;
            const float delay_i = ceilf(delay);
            const float fr      = delay_i - delay;     // [0,1)

            const float s = sinf(PI_F * fr);           // sin(pi*x) = s * (-1)^t
            float sA, cA;
            __sincosf(PI_F * (1.0f / 40.0f) * fr, &sA, &cA);

            frL   = fr;
            a2L   = amp * s * INV_PI_F;
            amL   = amp;
            hcL   = 0.5f * cA;
            hsL   = 0.5f * sA;
            baseL = (int)delay_i - 40;
        }

        // ---------- warp-cooperative tap scatter (conflict-free) ----------
        const int nv = min(32, ie - i0);
        for (int j = 0; j < nv; j++) {
            const float fr   = __shfl_sync(0xffffffffu, frL,   j);
            const float a2   = __shfl_sync(0xffffffffu, a2L,   j);
            const float am   = __shfl_sync(0xffffffffu, amL,   j);
            const float hc   = __shfl_sync(0xffffffffu, hcL,   j);
            const float hs   = __shfl_sync(0xffffffffu, hsL,   j);
            const int   base = __shfl_sync(0xffffffffu, baseL, j);
            const float a2s  = (lane & 1) ? -a2 : a2;  // (-1)^t, t = lane+32r
#pragma unroll
            for (int r = 0; r < 3; r++) {
                const int t = lane + 32 * r;
                if (t < 81) {
                    const float2 cs  = htab[t];
                    const float x    = fr + (float)(t - 40);
                    const float hann = fmaf(hc, cs.x, fmaf(-hs, cs.y, 0.5f));
                    const float sv   = (x == 0.0f) ? am : __fdividef(a2s, x);
                    const int   idx  = base + t;
                    if (x <= 40.0f && idx >= 0 && idx < RIR_LEN)
                        atomicAdd(&srir[idx], sv * hann);
                }
            }
        }
    }
    __syncthreads();

    // write this CTA's partial RIR (coalesced)
    float* prow = g_part + ((size_t)sub * MAXB + b) * RIR_LEN;
    for (int i = tid; i < RIR_LEN; i += NTH) prow[i] = srir[i];

    // TOA (once per room)
    if (sub == 0 && tid == 0) {
        const float d0 = micS[0] - srcS[0];
        const float d1 = micS[1] - srcS[1];
        const float d2 = micS[2] - srcS[2];
        out[(size_t)B * RIR_LEN + b] =
            40.0f + FS_OVER_C * sqrtf(d0 * d0 + d1 * d1 + d2 * d2);
    }
}

__global__ void __launch_bounds__(NTH)
rir_combine_kernel(float* __restrict__ out, int n)
{
    const int g = blockIdx.x * NTH + threadIdx.x;
    if (g < n) {
        const int S = MAXB * RIR_LEN;
        out[g] = (g_part[g] + g_part[g + S]) + (g_part[g + 2 * S] + g_part[g + 3 * S]);
    }
}

extern "C" void kernel_launch(void* const* d_in, const int* in_sizes, int n_in,
                              void* d_out, int out_size)
{
    const float* in  = (const float*)d_in[0];
    float*       out = (float*)d_out;
    const int B = in_sizes[0] / 10;          // 256 rooms x 10 params
    const int n = B * RIR_LEN;
    rir_partial_kernel<<<B * NSPLIT, NTH>>>(in, out, B);
    rir_combine_kernel<<<(n + NTH - 1) / NTH, NTH>>>(out, n);
}